// round 16
// baseline (speedup 1.0000x reference)
#include <cuda_runtime.h>
#include <cuda_fp16.h>
#include <cstdint>
#include <cstddef>

// ---------------------------------------------------------------------------
// Problem dims
// ---------------------------------------------------------------------------
constexpr int L    = 2048;
constexpr int HID  = 3072;
constexpr int H    = 24;
constexpr int D    = 128;
constexpr int LIP  = 64;
constexpr int CTX  = 4096;
constexpr int W1N  = 3 * HID + 4 * HID;   // 21504
constexpr int MLPD = 4 * HID;             // 12288
constexpr int FW   = HID + MLPD;          // 15360
constexpr int QKV  = 3 * HID;             // 9216
constexpr int KSPLIT = 4;
constexpr int K2   = FW / KSPLIT;         // 3840

// ---------------------------------------------------------------------------
// Float scratch
// ---------------------------------------------------------------------------
constexpr size_t O_MOD   = 0;                                   // 9216
constexpr size_t O_H     = O_MOD   + (size_t)3 * HID;           // L*W1N (linear2 partials)
constexpr size_t O_IPKR  = O_H     + (size_t)L * W1N;           // LIP*HID
constexpr size_t O_IPVR  = O_IPKR  + (size_t)LIP * HID;
constexpr size_t SCRATCH_F = O_IPVR + (size_t)LIP * HID;

__device__ __align__(16) float g_scratch[SCRATCH_F];

// ---------------------------------------------------------------------------
// Half scratch
// ---------------------------------------------------------------------------
constexpr size_t HQ = (size_t)H * L * D;
constexpr size_t OH_XMOD  = 0;                                   // L*HID
constexpr size_t OH_W1    = OH_XMOD  + (size_t)L * HID;          // W1N*HID
constexpr size_t OH_W2    = OH_W1    + (size_t)W1N * HID;        // HID*FW
constexpr size_t OH_IPKW  = OH_W2    + (size_t)HID * FW;         // HID*CTX
constexpr size_t OH_IPVW  = OH_IPKW  + (size_t)HID * CTX;
constexpr size_t OH_IP    = OH_IPVW  + (size_t)HID * CTX;        // LIP*CTX
constexpr size_t OH_QR    = OH_IP    + (size_t)LIP * CTX;        // HQ
constexpr size_t OH_KR    = OH_QR    + HQ;
constexpr size_t OH_QNR   = OH_KR    + HQ;
constexpr size_t OH_VT    = OH_QNR   + HQ;
constexpr size_t OH_IPK   = OH_VT    + HQ;                       // H*LIP*D
constexpr size_t OH_IPVT  = OH_IPK   + (size_t)H * LIP * D;
constexpr size_t OH_FUSED = OH_IPVT  + (size_t)H * LIP * D;      // L*FW
constexpr size_t OH_QKV   = OH_FUSED + (size_t)L * FW;           // L*QKV
constexpr size_t SCRATCH_H = OH_QKV + (size_t)L * QKV;

__device__ __align__(16) __half g_hscratch[SCRATCH_H];

// ---------------------------------------------------------------------------
// Helpers
// ---------------------------------------------------------------------------
__device__ __forceinline__ void mma16(float* c, const uint32_t* a,
                                      uint32_t b0, uint32_t b1) {
    asm volatile(
        "mma.sync.aligned.m16n8k16.row.col.f32.f16.f16.f32 "
        "{%0,%1,%2,%3}, {%4,%5,%6,%7}, {%8,%9}, {%0,%1,%2,%3};\n"
        : "+f"(c[0]), "+f"(c[1]), "+f"(c[2]), "+f"(c[3])
        : "r"(a[0]), "r"(a[1]), "r"(a[2]), "r"(a[3]),
          "r"(b0), "r"(b1));
}

__device__ __forceinline__ void ldsm_x4(uint32_t* r, uint32_t addr) {
    asm volatile("ldmatrix.sync.aligned.m8n8.x4.shared.b16 {%0,%1,%2,%3}, [%4];"
                 : "=r"(r[0]), "=r"(r[1]), "=r"(r[2]), "=r"(r[3])
                 : "r"(addr));
}

__device__ __forceinline__ void cp_async16(uint32_t dst, const void* src, bool pred) {
    int bytes = pred ? 16 : 0;
    asm volatile("cp.async.cg.shared.global [%0], [%1], 16, %2;\n"
                 :: "r"(dst), "l"(src), "r"(bytes));
}

__device__ __forceinline__ uint32_t pack_h2(float x, float y) {
    __half2 h = __floats2half2_rn(x, y);
    return *(uint32_t*)&h;
}

__device__ __forceinline__ float blockReduceSum(float v, float* sh) {
    #pragma unroll
    for (int o = 16; o; o >>= 1) v += __shfl_xor_sync(0xffffffffu, v, o);
    int lane = threadIdx.x & 31, w = threadIdx.x >> 5;
    __syncthreads();
    if (lane == 0) sh[w] = v;
    __syncthreads();
    float r = 0.f;
    int nw = blockDim.x >> 5;
    for (int i = 0; i < nw; i++) r += sh[i];
    return r;
}

__device__ __forceinline__ float gelu_tanh(float x) {
    float t  = 0.7978845608028654f * (x + 0.044715f * x * x * x);
    float th = 1.f - 2.f / (__expf(2.f * t) + 1.f);
    return 0.5f * x * (1.0f + th);
}

__device__ __forceinline__ float4 h4_to_f4(const __half* p) {
    uint2 u = *(const uint2*)p;
    __half2 a = *(__half2*)&u.x, b = *(__half2*)&u.y;
    return make_float4(__low2float(a), __high2float(a),
                       __low2float(b), __high2float(b));
}

// ---------------------------------------------------------------------------
// fp16 GEMM (128x128 tile), 256 threads (2x4 warps, warp tile 64x32),
// cp.async 4-stage ring, ldmatrix, 80B rows, 2 CTAs/SM.
// Epilogue selected at COMPILE TIME (EPI):
//   0: C = acc (+bias)  (f32)
//   1: cols <  fuseStart: half(acc+bias) -> ((half*)C)[row*QKV + col]
//      cols >= fuseStart: gelu(acc+bias) -> half -> gOut[row][HID+col-fuseStart]
// ---------------------------------------------------------------------------
constexpr int GSTAGES   = 4;
constexpr int ROWB      = 80;
constexpr int TILE_B    = 128 * ROWB;           // 10240
constexpr int STAGE_B   = 2 * TILE_B;           // 20480
constexpr uint32_t GEMM_SMEM = GSTAGES * STAGE_B;   // 80KB

template <int EPI>
__global__ void __launch_bounds__(256, 2) gemm_f16_kernel(
    const __half* __restrict__ A, const __half* __restrict__ B,
    float* __restrict__ C, const float* __restrict__ bias,
    int M, int N, int K, int lda, int ldb, int ldc,
    size_t sA, size_t sB, size_t sC,
    int nTiles, int mc,
    __half* __restrict__ gOut, int fuseStart)
{
    extern __shared__ __align__(128) uint8_t dsm[];
    uint32_t smBase = (uint32_t)__cvta_generic_to_shared(dsm);

    A += (size_t)blockIdx.z * sA;
    B += (size_t)blockIdx.z * sB;
    C += (size_t)blockIdx.z * sC;

    int bx    = blockIdx.x;
    int per   = mc * nTiles;
    int chunk = bx / per;
    int rem   = bx - chunk * per;
    int nTile = rem / mc;
    int mTile = chunk * mc + (rem - nTile * mc);
    int aBase = mTile * 128;
    int bBase = nTile * 128;

    int tid  = threadIdx.x;
    int lane = tid & 31, warp = tid >> 5;
    int wm   = warp >> 2, wn = warp & 3;

    int kt = K >> 5;

    int r0  = tid >> 2;
    int r1  = r0 + 64;
    int c16 = tid & 3;
    bool pa0 = aBase + r0 < M, pa1 = aBase + r1 < M;
    bool pb0 = bBase + r0 < N, pb1 = bBase + r1 < N;
    const __half* Ap0 = A + (size_t)(pa0 ? aBase + r0 : 0) * lda + c16 * 8;
    const __half* Ap1 = A + (size_t)(pa1 ? aBase + r1 : 0) * lda + c16 * 8;
    const __half* Bp0 = B + (size_t)(pb0 ? bBase + r0 : 0) * ldb + c16 * 8;
    const __half* Bp1 = B + (size_t)(pb1 ? bBase + r1 : 0) * ldb + c16 * 8;

    uint32_t off0 = (uint32_t)(r0 * ROWB + c16 * 16);
    uint32_t off1 = (uint32_t)(r1 * ROWB + c16 * 16);

    uint32_t aOff = (uint32_t)((wm * 64 + (lane & 15)) * ROWB + (lane >> 4) * 16);
    uint32_t bOff = (uint32_t)(TILE_B + (wn * 32 + (lane & 15)) * ROWB + (lane >> 4) * 16);

#define GEMM_PREF(itv) do {                                                   \
    int _it = (itv);                                                          \
    if (_it < kt) {                                                           \
        int _ko = _it << 5;                                                   \
        uint32_t _sA = smBase + (uint32_t)(_it % GSTAGES) * STAGE_B;          \
        uint32_t _sB = _sA + (uint32_t)TILE_B;                                \
        cp_async16(_sA + off0, Ap0 + _ko, pa0);                               \
        cp_async16(_sA + off1, Ap1 + _ko, pa1);                               \
        cp_async16(_sB + off0, Bp0 + _ko, pb0);                               \
        cp_async16(_sB + off1, Bp1 + _ko, pb1);                               \
    }                                                                         \
    asm volatile("cp.async.commit_group;\n" ::);                              \
} while (0)

    float acc[4][4][4];
    #pragma unroll
    for (int i = 0; i < 4; i++)
        #pragma unroll
        for (int j = 0; j < 4; j++)
            #pragma unroll
            for (int t = 0; t < 4; t++) acc[i][j][t] = 0.f;

    GEMM_PREF(0);
    GEMM_PREF(1);
    GEMM_PREF(2);

    for (int it = 0; it < kt; ++it) {
        asm volatile("cp.async.wait_group 2;\n" ::);
        __syncthreads();
        GEMM_PREF(it + 3);

        uint32_t stage = smBase + (uint32_t)(it % GSTAGES) * STAGE_B;
        uint32_t aA = stage + aOff;
        uint32_t bA = stage + bOff;

        #pragma unroll
        for (int kk = 0; kk < 2; kk++) {
            uint32_t a[4][4], b[2][4];
            #pragma unroll
            for (int mt = 0; mt < 4; mt++)
                ldsm_x4(a[mt], aA + mt * (16 * ROWB) + kk * 32);
            #pragma unroll
            for (int np = 0; np < 2; np++)
                ldsm_x4(b[np], bA + np * (16 * ROWB) + kk * 32);
            #pragma unroll
            for (int mt = 0; mt < 4; mt++)
                #pragma unroll
                for (int nt = 0; nt < 4; nt++)
                    mma16(acc[mt][nt], a[mt],
                          b[nt >> 1][nt & 1], b[nt >> 1][(nt & 1) + 2]);
        }
    }
#undef GEMM_PREF

    int gid = lane >> 2, tig = lane & 3;
    #pragma unroll
    for (int mt = 0; mt < 4; mt++) {
        #pragma unroll
        for (int nt = 0; nt < 4; nt++) {
            int row = aBase + wm * 64 + mt * 16 + gid;
            int col = bBase + wn * 32 + nt * 8 + tig * 2;
            if (col < N) {
                float b0 = 0.f, b1 = 0.f;
                if (bias) { b0 = bias[col]; b1 = bias[col + 1]; }
                float v0 = acc[mt][nt][0] + b0, v1 = acc[mt][nt][1] + b1;
                float v2 = acc[mt][nt][2] + b0, v3 = acc[mt][nt][3] + b1;
                if constexpr (EPI == 1) {
                    if (col >= fuseStart) {
                        int fcol = HID + col - fuseStart;
                        if (row < M)
                            *(__half2*)(gOut + (size_t)row * FW + fcol) =
                                __floats2half2_rn(gelu_tanh(v0), gelu_tanh(v1));
                        if (row + 8 < M)
                            *(__half2*)(gOut + (size_t)(row + 8) * FW + fcol) =
                                __floats2half2_rn(gelu_tanh(v2), gelu_tanh(v3));
                    } else {
                        __half* qk = (__half*)C;
                        if (row < M)
                            *(__half2*)(qk + (size_t)row * QKV + col) =
                                __floats2half2_rn(v0, v1);
                        if (row + 8 < M)
                            *(__half2*)(qk + (size_t)(row + 8) * QKV + col) =
                                __floats2half2_rn(v2, v3);
                    }
                } else {
                    if (row < M) {
                        C[(size_t)row * ldc + col]     = v0;
                        C[(size_t)row * ldc + col + 1] = v1;
                    }
                    if (row + 8 < M) {
                        C[(size_t)(row + 8) * ldc + col]     = v2;
                        C[(size_t)(row + 8) * ldc + col + 1] = v3;
                    }
                }
            }
        }
    }
}

// ---------------------------------------------------------------------------
// Flash attention (self-attn) + fused ip attention + combine.
// Per CTA = (head, 128-row Q block). After the main 16-iter loop, smem is
// reloaded with qnr / ipk / ipvt and the 64-key ip attention runs; the
// combined half result goes directly into the fused buffer.
// ---------------------------------------------------------------------------
constexpr int FROWB = 272;
constexpr uint32_t FTILE = 128 * FROWB;             // 34816
constexpr uint32_t FLASH_SMEM = 3 * FTILE;          // 104448

__global__ void __launch_bounds__(256) flash_kernel(
    const __half* __restrict__ Qg, const __half* __restrict__ Kg,
    const __half* __restrict__ Vg,
    const __half* __restrict__ Qn, const __half* __restrict__ Kip,
    const __half* __restrict__ Vip,
    const float* __restrict__ ip_scale, __half* __restrict__ fused)
{
    extern __shared__ __align__(128) uint8_t fsm[];
    uint32_t sQ = (uint32_t)__cvta_generic_to_shared(fsm);
    uint32_t sK = sQ + FTILE;
    uint32_t sV = sK + FTILE;

    int head = blockIdx.y;
    int qb   = blockIdx.x * 128;
    const __half* Qp = Qg + ((size_t)head * L + qb) * D;
    const __half* Kp = Kg + (size_t)head * L * D;
    const __half* Vp = Vg + (size_t)head * D * L;

    int tid = threadIdx.x, lane = tid & 31, warp = tid >> 5;
    int lr = tid >> 1;
    int lc = (tid & 1) * 8;
    uint32_t ldst = (uint32_t)(lr * FROWB + lc * 16);

#define FLOAD(dst, gbase, gstride) do {                                       \
    const __half* _g = (gbase) + (size_t)lr * (gstride) + lc * 8;             \
    _Pragma("unroll")                                                         \
    for (int _j = 0; _j < 8; _j++)                                            \
        cp_async16((dst) + ldst + _j * 16, _g + _j * 8, true);                \
} while (0)

    FLOAD(sQ, Qp, D);
    FLOAD(sK, Kp, D);
    asm volatile("cp.async.commit_group;\n" ::);
    FLOAD(sV, Vp, L);
    asm volatile("cp.async.commit_group;\n" ::);
    asm volatile("cp.async.wait_group 1;\n" ::);
    __syncthreads();

    uint32_t qf[8][4];
    {
        uint32_t qa = sQ + (uint32_t)((warp * 16 + (lane & 15)) * FROWB
                                      + (lane >> 4) * 16);
        #pragma unroll
        for (int kk = 0; kk < 8; kk++) ldsm_x4(qf[kk], qa + kk * 32);
    }

    float o[16][4];
    #pragma unroll
    for (int i = 0; i < 16; i++) { o[i][0] = o[i][1] = o[i][2] = o[i][3] = 0.f; }
    float mr0 = -1e30f, mr1 = -1e30f, l0 = 0.f, l1 = 0.f;

    uint32_t kba = sK + (uint32_t)((lane & 15) * FROWB + (lane >> 4) * 16);
    uint32_t vba = sV + (uint32_t)((lane & 15) * FROWB + (lane >> 4) * 16);

    constexpr int NKB = L / 128;    // 16
    for (int kb = 0; kb < NKB; kb++) {
        float s[16][4];
        #pragma unroll
        for (int i = 0; i < 16; i++) { s[i][0] = s[i][1] = s[i][2] = s[i][3] = 0.f; }
        #pragma unroll
        for (int kk = 0; kk < 8; kk++) {
            #pragma unroll
            for (int np = 0; np < 8; np++) {
                uint32_t b[4];
                ldsm_x4(b, kba + np * (16 * FROWB) + kk * 32);
                mma16(s[2 * np],     qf[kk], b[0], b[2]);
                mma16(s[2 * np + 1], qf[kk], b[1], b[3]);
            }
        }
        __syncthreads();
        if (kb + 1 < NKB) FLOAD(sK, Kp + (size_t)(kb + 1) * 128 * D, D);
        asm volatile("cp.async.commit_group;\n" ::);

        float m0 = -1e30f, m1 = -1e30f;
        #pragma unroll
        for (int ng = 0; ng < 16; ng++) {
            m0 = fmaxf(m0, fmaxf(s[ng][0], s[ng][1]));
            m1 = fmaxf(m1, fmaxf(s[ng][2], s[ng][3]));
        }
        m0 = fmaxf(m0, __shfl_xor_sync(0xffffffffu, m0, 1));
        m0 = fmaxf(m0, __shfl_xor_sync(0xffffffffu, m0, 2));
        m1 = fmaxf(m1, __shfl_xor_sync(0xffffffffu, m1, 1));
        m1 = fmaxf(m1, __shfl_xor_sync(0xffffffffu, m1, 2));
        float nm0 = fmaxf(mr0, m0), nm1 = fmaxf(mr1, m1);
        float a0 = __expf(mr0 - nm0), a1 = __expf(mr1 - nm1);
        mr0 = nm0; mr1 = nm1;
        float ps0 = 0.f, ps1 = 0.f;
        #pragma unroll
        for (int ng = 0; ng < 16; ng++) {
            s[ng][0] = __expf(s[ng][0] - nm0);
            s[ng][1] = __expf(s[ng][1] - nm0);
            s[ng][2] = __expf(s[ng][2] - nm1);
            s[ng][3] = __expf(s[ng][3] - nm1);
            ps0 += s[ng][0] + s[ng][1];
            ps1 += s[ng][2] + s[ng][3];
            o[ng][0] *= a0; o[ng][1] *= a0;
            o[ng][2] *= a1; o[ng][3] *= a1;
        }
        l0 = l0 * a0 + ps0;
        l1 = l1 * a1 + ps1;

        uint32_t pa[8][4];
        #pragma unroll
        for (int kk = 0; kk < 8; kk++) {
            pa[kk][0] = pack_h2(s[2 * kk][0],     s[2 * kk][1]);
            pa[kk][1] = pack_h2(s[2 * kk][2],     s[2 * kk][3]);
            pa[kk][2] = pack_h2(s[2 * kk + 1][0], s[2 * kk + 1][1]);
            pa[kk][3] = pack_h2(s[2 * kk + 1][2], s[2 * kk + 1][3]);
        }

        asm volatile("cp.async.wait_group 1;\n" ::);
        __syncthreads();

        #pragma unroll
        for (int kk = 0; kk < 8; kk++) {
            #pragma unroll
            for (int np = 0; np < 8; np++) {
                uint32_t b[4];
                ldsm_x4(b, vba + np * (16 * FROWB) + kk * 32);
                mma16(o[2 * np],     pa[kk], b[0], b[2]);
                mma16(o[2 * np + 1], pa[kk], b[1], b[3]);
            }
        }
        __syncthreads();
        if (kb + 1 < NKB) FLOAD(sV, Vp + (kb + 1) * 128, L);
        asm volatile("cp.async.commit_group;\n" ::);
        asm volatile("cp.async.wait_group 1;\n" ::);
        __syncthreads();
    }
#undef FLOAD

    l0 += __shfl_xor_sync(0xffffffffu, l0, 1);
    l0 += __shfl_xor_sync(0xffffffffu, l0, 2);
    l1 += __shfl_xor_sync(0xffffffffu, l1, 1);
    l1 += __shfl_xor_sync(0xffffffffu, l1, 2);

    // -------------------- ip attention (64 keys) --------------------
    // smem is free; load qnr tile -> sQ, ipk -> sK, ipvt -> sV.
    {
        const __half* Q2p = Qn + ((size_t)head * L + qb) * D;
        const __half* K2p = Kip + (size_t)head * LIP * D;
        const __half* V2p = Vip + (size_t)head * D * LIP;
        {
            const __half* g = Q2p + (size_t)lr * D + lc * 8;
            #pragma unroll
            for (int j = 0; j < 8; j++)
                cp_async16(sQ + ldst + j * 16, g + j * 8, true);
        }
        {
            int kr = tid >> 2, kc = (tid & 3) * 4;
            const __half* g = K2p + (size_t)kr * D + kc * 8;
            uint32_t dst = sK + (uint32_t)(kr * FROWB + kc * 16);
            #pragma unroll
            for (int j = 0; j < 4; j++) cp_async16(dst + j * 16, g + j * 8, true);
        }
        {
            int vr = tid >> 1, vc = (tid & 1) * 4;
            const __half* g = V2p + (size_t)vr * LIP + vc * 8;
            uint32_t dst = sV + (uint32_t)(vr * FROWB + vc * 16);
            #pragma unroll
            for (int j = 0; j < 4; j++) cp_async16(dst + j * 16, g + j * 8, true);
        }
        asm volatile("cp.async.commit_group;\n" ::);
        asm volatile("cp.async.wait_group 0;\n" ::);
        __syncthreads();
    }

    // qnr fragments
    {
        uint32_t qa = sQ + (uint32_t)((warp * 16 + (lane & 15)) * FROWB
                                      + (lane >> 4) * 16);
        #pragma unroll
        for (int kk = 0; kk < 8; kk++) ldsm_x4(qf[kk], qa + kk * 32);
    }

    float s2[8][4];
    #pragma unroll
    for (int i = 0; i < 8; i++) { s2[i][0] = s2[i][1] = s2[i][2] = s2[i][3] = 0.f; }
    #pragma unroll
    for (int kk = 0; kk < 8; kk++) {
        #pragma unroll
        for (int np = 0; np < 4; np++) {
            uint32_t b[4];
            ldsm_x4(b, kba + np * (16 * FROWB) + kk * 32);
            mma16(s2[2 * np],     qf[kk], b[0], b[2]);
            mma16(s2[2 * np + 1], qf[kk], b[1], b[3]);
        }
    }

    float im0 = -1e30f, im1 = -1e30f;
    #pragma unroll
    for (int ng = 0; ng < 8; ng++) {
        im0 = fmaxf(im0, fmaxf(s2[ng][0], s2[ng][1]));
        im1 = fmaxf(im1, fmaxf(s2[ng][2], s2[ng][3]));
    }
    im0 = fmaxf(im0, __shfl_xor_sync(0xffffffffu, im0, 1));
    im0 = fmaxf(im0, __shfl_xor_sync(0xffffffffu, im0, 2));
    im1 = fmaxf(im1, __shfl_xor_sync(0xffffffffu, im1, 1));
    im1 = fmaxf(im1, __shfl_xor_sync(0xffffffffu, im1, 2));
    float il0 = 0.f, il1 = 0.f;
    #pragma unroll
    for (int ng = 0; ng < 8; ng++) {
        s2[ng][0] = __expf(s2[ng][0] - im0);
        s2[ng][1] = __expf(s2[ng][1] - im0);
        s2[ng][2] = __expf(s2[ng][2] - im1);
        s2[ng][3] = __expf(s2[ng][3] - im1);
        il0 += s2[ng][0] + s2[ng][1];
        il1 += s2[ng][2] + s2[ng][3];
    }
    uint32_t pa2[4][4];
    #pragma unroll
    for (int kk = 0; kk < 4; kk++) {
        pa2[kk][0] = pack_h2(s2[2 * kk][0],     s2[2 * kk][1]);
        pa2[kk][1] = pack_h2(s2[2 * kk][2],     s2[2 * kk][3]);
        pa2[kk][2] = pack_h2(s2[2 * kk + 1][0], s2[2 * kk + 1][1]);
        pa2[kk][3] = pack_h2(s2[2 * kk + 1][2], s2[2 * kk + 1][3]);
    }

    float o2[16][4];
    #pragma unroll
    for (int i = 0; i < 16; i++) { o2[i][0] = o2[i][1] = o2[i][2] = o2[i][3] = 0.f; }
    #pragma unroll
    for (int kk = 0; kk < 4; kk++) {
        #pragma unroll
        for (int np = 0; np < 8; np++) {
            uint32_t b[4];
            ldsm_x4(b, vba + np * (16 * FROWB) + kk * 32);
            mma16(o2[2 * np],     pa2[kk], b[0], b[2]);
            mma16(o2[2 * np + 1], pa2[kk], b[1], b[3]);
        }
    }

    il0 += __shfl_xor_sync(0xffffffffu, il0, 1);
    il0 += __shfl_xor_sync(0xffffffffu, il0, 2);
    il1 += __shfl_xor_sync(0xffffffffu, il1, 1);
    il1 += __shfl_xor_sync(0xffffffffu, il1, 2);

    float sc = ip_scale[0];
    float invM0 = 1.f / l0,  invM1 = 1.f / l1;
    float invI0 = sc / il0,  invI1 = sc / il1;
    int gid = lane >> 2, tig = lane & 3;
    int r0 = qb + warp * 16 + gid;
    __half* F0 = fused + (size_t)r0 * FW + head * D;
    __half* F1 = F0 + (size_t)8 * FW;
    #pragma unroll
    for (int ng = 0; ng < 16; ng++) {
        int col = ng * 8 + tig * 2;
        *(__half2*)(F0 + col) = __floats2half2_rn(
            o[ng][0] * invM0 + o2[ng][0] * invI0,
            o[ng][1] * invM0 + o2[ng][1] * invI0);
        *(__half2*)(F1 + col) = __floats2half2_rn(
            o[ng][2] * invM1 + o2[ng][2] * invI1,
            o[ng][3] * invM1 + o2[ng][3] * invI1);
    }
}

// ---------------------------------------------------------------------------
// float -> half conversion, 8 elems per thread
// ---------------------------------------------------------------------------
__global__ __launch_bounds__(256) void f2h_kernel(
    const float* __restrict__ in, __half* __restrict__ out, int n)
{
    int i = (blockIdx.x * 256 + threadIdx.x) * 8;
    if (i < n) {
        float4 a = *(const float4*)(in + i);
        float4 b = *(const float4*)(in + i + 4);
        __half2 h[4];
        h[0] = __floats2half2_rn(a.x, a.y);
        h[1] = __floats2half2_rn(a.z, a.w);
        h[2] = __floats2half2_rn(b.x, b.y);
        h[3] = __floats2half2_rn(b.z, b.w);
        *(uint4*)(out + i) = *(uint4*)h;
    }
}

// ---------------------------------------------------------------------------
// mod = silu(vec) @ mod_lin_w^T + mod_lin_b
// ---------------------------------------------------------------------------
__global__ __launch_bounds__(256) void mod_gemv_kernel(
    const float* __restrict__ vec, const float* __restrict__ W,
    const float* __restrict__ b, float* __restrict__ mod)
{
    __shared__ float sv[HID];
    int tid = threadIdx.x;
    for (int i = tid; i < HID; i += 256) {
        float x = vec[i];
        sv[i] = x / (1.f + __expf(-x));
    }
    __syncthreads();
    int warp = tid >> 5, lane = tid & 31;
    int n = blockIdx.x * 8 + warp;
    const float* wrow = W + (size_t)n * HID;
    float s = 0.f;
    for (int k = lane * 4; k < HID; k += 128) {
        float4 w4 = *(const float4*)(wrow + k);
        s += sv[k] * w4.x + sv[k + 1] * w4.y + sv[k + 2] * w4.z + sv[k + 3] * w4.w;
    }
    #pragma unroll
    for (int o = 16; o; o >>= 1) s += __shfl_xor_sync(0xffffffffu, s, o);
    if (lane == 0) mod[n] = s + b[n];
}

// ---------------------------------------------------------------------------
// x_mod = (1+scale)*layernorm(x) + shift  -> half
// ---------------------------------------------------------------------------
__global__ __launch_bounds__(256) void ln_mod_kernel(
    const float* __restrict__ x, const float* __restrict__ mod,
    __half* __restrict__ xmod)
{
    __shared__ float sh[8];
    int l = blockIdx.x, tid = threadIdx.x;
    const float* row = x + (size_t)l * HID;
    float v[12];
    float s = 0.f, sq = 0.f;
    #pragma unroll
    for (int i = 0; i < 12; i++) {
        v[i] = row[tid + i * 256];
        s += v[i];
        sq += v[i] * v[i];
    }
    s  = blockReduceSum(s, sh);
    sq = blockReduceSum(sq, sh);
    float mu   = s * (1.f / HID);
    float var  = sq * (1.f / HID) - mu * mu;
    float rstd = rsqrtf(var + 1e-6f);
    #pragma unroll
    for (int i = 0; i < 12; i++) {
        int c = tid + i * 256;
        float xn = (v[i] - mu) * rstd;
        xmod[(size_t)l * HID + c] = __float2half((1.f + mod[HID + c]) * xn + mod[c]);
    }
}

// ---------------------------------------------------------------------------
// rmsnorm(q,k) + rope + repack, reading half QKV. One warp per (head, l);
// block = 8 consecutive l of ONE head. vt staged via smem, coalesced writes.
// ---------------------------------------------------------------------------
__global__ __launch_bounds__(256) void rms_rope_kernel(
    const __half* __restrict__ qkv, const float* __restrict__ pe,
    const float* __restrict__ qsc, const float* __restrict__ ksc,
    __half* __restrict__ qr, __half* __restrict__ kr,
    __half* __restrict__ qnr, __half* __restrict__ vt)
{
    __shared__ float sv[8][132];
    int tid = threadIdx.x, lane = tid & 31, warp = tid >> 5;
    int g = blockIdx.x * 8 + warp;          // g = head * L + l
    int head = g >> 11;                     // L = 2048
    int l    = g & (L - 1);

    const __half* base = qkv + (size_t)l * QKV + head * D + lane * 4;
    float4 q = h4_to_f4(base);
    float4 k = h4_to_f4(base + HID);
    float4 v = h4_to_f4(base + 2 * HID);

    float sq = q.x * q.x + q.y * q.y + q.z * q.z + q.w * q.w;
    float sk = k.x * k.x + k.y * k.y + k.z * k.z + k.w * k.w;
    #pragma unroll
    for (int o = 16; o; o >>= 1) {
        sq += __shfl_xor_sync(0xffffffffu, sq, o);
        sk += __shfl_xor_sync(0xffffffffu, sk, o);
    }
    float rq = rsqrtf(sq * (1.f / D) + 1e-6f) * 0.08838834764831845f;
    float rk = rsqrtf(sk * (1.f / D) + 1e-6f);

    float4 qs4 = *(const float4*)(qsc + lane * 4);
    float4 ks4 = *(const float4*)(ksc + lane * 4);
    float4 qn = make_float4(q.x * rq * qs4.x, q.y * rq * qs4.y,
                            q.z * rq * qs4.z, q.w * rq * qs4.w);
    float4 kn = make_float4(k.x * rk * ks4.x, k.y * rk * ks4.y,
                            k.z * rk * ks4.z, k.w * rk * ks4.w);

    size_t oidx = ((size_t)head * L + l) * D + lane * 4;
    *(__half2*)(qnr + oidx)     = __floats2half2_rn(qn.x, qn.y);
    *(__half2*)(qnr + oidx + 2) = __floats2half2_rn(qn.z, qn.w);

    const float* pb = pe + ((size_t)l * (D / 2) + lane * 2) * 4;
    float4 p0 = *(const float4*)(pb);
    float4 p1 = *(const float4*)(pb + 4);

    float4 qo, ko;
    qo.x = p0.x * qn.x + p0.y * qn.y;  qo.y = p0.z * qn.x + p0.w * qn.y;
    qo.z = p1.x * qn.z + p1.y * qn.w;  qo.w = p1.z * qn.z + p1.w * qn.w;
    ko.x = p0.x * kn.x + p0.y * kn.y;  ko.y = p0.z * kn.x + p0.w * kn.y;
    ko.z = p1.x * kn.z + p1.y * kn.w;  ko.w = p1.z * kn.z + p1.w * kn.w;

    *(__half2*)(qr + oidx)     = __floats2half2_rn(qo.x, qo.y);
    *(__half2*)(qr + oidx + 2) = __floats2half2_rn(qo.z, qo.w);
    *(__half2*)(kr + oidx)     = __floats2half2_rn(ko.x, ko.y);
    *(__half2*)(kr + oidx + 2) = __floats2half2_rn(ko.z, ko.w);

    sv[warp][lane * 4]     = v.x;
    sv[warp][lane * 4 + 1] = v.y;
    sv[warp][lane * 4 + 2] = v.z;
    sv[warp][lane * 4 + 3] = v.w;
    __syncthreads();
    if (tid < D) {
        int d = tid;
        int l0 = (blockIdx.x * 8) & (L - 1);
        __half hv[8];
        #pragma unroll
        for (int j = 0; j < 8; j++) hv[j] = __float2half(sv[j][d]);
        *(uint4*)(vt + ((size_t)head * D + d) * L + l0) = *(uint4*)hv;
    }
}

// ---------------------------------------------------------------------------
// repack ip_k / ip_v GEMM outputs into per-head half layouts
// ---------------------------------------------------------------------------
__global__ __launch_bounds__(256) void repack_ip_kernel(
    const float* __restrict__ kraw, const float* __restrict__ vraw,
    __half* __restrict__ ipk, __half* __restrict__ ipvt)
{
    int i = blockIdx.x * 256 + threadIdx.x;
    int d = i & (D - 1);
    int lip = (i >> 7) & (LIP - 1);
    int head = i >> 13;
    size_t src = (size_t)lip * HID + head * D + d;
    ipk[((size_t)head * LIP + lip) * D + d]  = __float2half(kraw[src]);
    ipvt[((size_t)head * D + d) * LIP + lip] = __float2half(vraw[src]);
}

// ---------------------------------------------------------------------------
// split-K combine: out = x + gate[col] * (bias[col] + p0 + p1 + p2 + p3)
// NOTE: HID is NOT a power of two; col must use true modulo.
// ---------------------------------------------------------------------------
__global__ __launch_bounds__(256) void splitk_combine_kernel(
    const float* __restrict__ parts, const float* __restrict__ x,
    const float* __restrict__ mod_gate, const float* __restrict__ bias,
    float* __restrict__ out)
{
    int i4 = (blockIdx.x * 256 + threadIdx.x) * 4;     // < L*HID
    int col = i4 - (i4 / HID) * HID;
    const float4 p0 = *(const float4*)(parts + i4);
    const float4 p1 = *(const float4*)(parts + (size_t)L * HID + i4);
    const float4 p2 = *(const float4*)(parts + (size_t)2 * L * HID + i4);
    const float4 p3 = *(const float4*)(parts + (size_t)3 * L * HID + i4);
    const float4 xb = *(const float4*)(x + i4);
    const float4 gb = *(const float4*)(mod_gate + col);
    const float4 bb = *(const float4*)(bias + col);
    float4 r;
    r.x = xb.x + gb.x * (bb.x + p0.x + p1.x + p2.x + p3.x);
    r.y = xb.y + gb.y * (bb.y + p0.y + p1.y + p2.y + p3.y);
    r.z = xb.z + gb.z * (bb.z + p0.z + p1.z + p2.z + p3.z);
    r.w = xb.w + gb.w * (bb.w + p0.w + p1.w + p2.w + p3.w);
    *(float4*)(out + i4) = r;
}

// ---------------------------------------------------------------------------
// host side
// ---------------------------------------------------------------------------
template <int EPI>
static void launch_gemm_t(const __half* A, const __half* B, float* C, const float* bias,
                          int M, int N, int K, int lda, int ldb, int ldc,
                          size_t sA, size_t sB, size_t sC, int batch, int mc,
                          __half* gOut = nullptr, int fuseStart = 0)
{
    int mTiles = (M + 127) / 128, nTiles = (N + 127) / 128;
    if (mc > mTiles) mc = mTiles;
    dim3 grid(mTiles * nTiles, 1, batch);
    gemm_f16_kernel<EPI><<<grid, 256, GEMM_SMEM>>>(
        A, B, C, bias, M, N, K, lda, ldb, ldc,
        sA, sB, sC, nTiles, mc, gOut, fuseStart);
}

static void launch_f2h(const float* in, __half* out, size_t n)
{
    int blocks = (int)((n / 8 + 255) / 256);
    f2h_kernel<<<blocks, 256>>>(in, out, (int)n);
}

extern "C" void kernel_launch(void* const* d_in, const int* in_sizes, int n_in,
                              void* d_out, int out_size)
{
    const float* x          = (const float*)d_in[0];
    const float* vec        = (const float*)d_in[1];
    const float* pe         = (const float*)d_in[2];
    const float* image_proj = (const float*)d_in[3];
    const float* ip_scale   = (const float*)d_in[4];
    const float* mod_w      = (const float*)d_in[5];
    const float* mod_b      = (const float*)d_in[6];
    const float* w1         = (const float*)d_in[7];
    const float* b1         = (const float*)d_in[8];
    const float* w2         = (const float*)d_in[9];
    const float* b2         = (const float*)d_in[10];
    const float* qsc        = (const float*)d_in[11];
    const float* ksc        = (const float*)d_in[12];
    const float* ipkw       = (const float*)d_in[13];
    const float* ipvw       = (const float*)d_in[14];
    float* out = (float*)d_out;

    cudaFuncSetAttribute(gemm_f16_kernel<0>,
                         cudaFuncAttributeMaxDynamicSharedMemorySize, GEMM_SMEM);
    cudaFuncSetAttribute(gemm_f16_kernel<1>,
                         cudaFuncAttributeMaxDynamicSharedMemorySize, GEMM_SMEM);
    cudaFuncSetAttribute(flash_kernel,
                         cudaFuncAttributeMaxDynamicSharedMemorySize, FLASH_SMEM);

    float* sc = nullptr;
    cudaGetSymbolAddress((void**)&sc, g_scratch);
    __half* hs = nullptr;
    cudaGetSymbolAddress((void**)&hs, g_hscratch);

    float* mod    = sc + O_MOD;
    float* ipkr   = sc + O_IPKR;
    float* ipvr   = sc + O_IPVR;
    float* parts  = sc + O_H;

    __half* h_xmod  = hs + OH_XMOD;
    __half* h_w1    = hs + OH_W1;
    __half* h_w2    = hs + OH_W2;
    __half* h_ipkw  = hs + OH_IPKW;
    __half* h_ipvw  = hs + OH_IPVW;
    __half* h_ip    = hs + OH_IP;
    __half* h_qr    = hs + OH_QR;
    __half* h_kr    = hs + OH_KR;
    __half* h_qnr   = hs + OH_QNR;
    __half* h_vt    = hs + OH_VT;
    __half* h_ipk   = hs + OH_IPK;
    __half* h_ipvt  = hs + OH_IPVT;
    __half* h_fused = hs + OH_FUSED;
    __half* h_qkv   = hs + OH_QKV;

    // [0] modulation vector
    mod_gemv_kernel<<<(3 * HID) / 8, 256>>>(vec, mod_w, mod_b, mod);
    // [1] w1 -> half
    launch_f2h(w1, h_w1, (size_t)W1N * HID);
    // [2] layernorm + modulate -> half
    ln_mod_kernel<<<L, 256>>>(x, mod, h_xmod);
    // [3] linear1: qkv -> half buffer, mlp -> gelu half into fused (ncu target)
    launch_gemm_t<1>(h_xmod, h_w1, (float*)h_qkv, b1, L, W1N, HID, HID, HID, W1N,
                     0, 0, 0, 1, 16, h_fused, QKV);
    // remaining conversions
    launch_f2h(w2, h_w2, (size_t)HID * FW);
    launch_f2h(ipkw, h_ipkw, (size_t)HID * CTX);
    launch_f2h(ipvw, h_ipvw, (size_t)HID * CTX);
    launch_f2h(image_proj, h_ip, (size_t)LIP * CTX);
    // rmsnorm + rope + repack (half in/out)
    rms_rope_kernel<<<(H * L) / 8, 256>>>(h_qkv, pe, qsc, ksc, h_qr, h_kr, h_qnr, h_vt);
    // ip_k / ip_v projections, batched (z=2)
    launch_gemm_t<0>(h_ip, h_ipkw, ipkr, nullptr, LIP, HID, CTX, CTX, CTX, HID,
                     0, (size_t)HID * CTX, (size_t)LIP * HID, 2, 1);
    repack_ip_kernel<<<(H * LIP * D) / 256, 256>>>(ipkr, ipvr, h_ipk, h_ipvt);
    // fused self-attention + ip attention + combine -> fused (half)
    flash_kernel<<<dim3(L / 128, H), 256, FLASH_SMEM>>>(
        h_qr, h_kr, h_vt, h_qnr, h_ipk, h_ipvt, ip_scale, h_fused);
    // linear2 split-K=4
    launch_gemm_t<0>(h_fused, h_w2, parts, nullptr, L, HID, K2, FW, FW, HID,
                     (size_t)K2, (size_t)K2, (size_t)L * HID, KSPLIT, 8);
    // combine partials + bias + gate + residual -> out
    splitk_combine_kernel<<<(L * HID / 4) / 256, 256>>>(parts, x, mod + 2 * HID, b2, out);
}

// round 17
// speedup vs baseline: 1.5007x; 1.5007x over previous
#include <cuda_runtime.h>
#include <cuda_fp16.h>
#include <cstdint>
#include <cstddef>

// ---------------------------------------------------------------------------
// Problem dims
// ---------------------------------------------------------------------------
constexpr int L    = 2048;
constexpr int HID  = 3072;
constexpr int H    = 24;
constexpr int D    = 128;
constexpr int LIP  = 64;
constexpr int CTX  = 4096;
constexpr int W1N  = 3 * HID + 4 * HID;   // 21504
constexpr int MLPD = 4 * HID;             // 12288
constexpr int FW   = HID + MLPD;          // 15360
constexpr int QKV  = 3 * HID;             // 9216
constexpr int KSPLIT = 4;
constexpr int K2   = FW / KSPLIT;         // 3840

// ---------------------------------------------------------------------------
// Float scratch
// ---------------------------------------------------------------------------
constexpr size_t O_MOD   = 0;                                   // 9216
constexpr size_t O_H     = O_MOD   + (size_t)3 * HID;           // 4*L*HID partials
constexpr size_t O_ATTN1 = O_H     + (size_t)KSPLIT * L * HID;  // H*L*D
constexpr size_t O_IPKR  = O_ATTN1 + (size_t)H * L * D;         // LIP*HID
constexpr size_t O_IPVR  = O_IPKR  + (size_t)LIP * HID;
constexpr size_t SCRATCH_F = O_IPVR + (size_t)LIP * HID;

__device__ __align__(16) float g_scratch[SCRATCH_F];

// ---------------------------------------------------------------------------
// Half scratch
// ---------------------------------------------------------------------------
constexpr size_t HQ = (size_t)H * L * D;
constexpr size_t OH_XMOD  = 0;                                   // L*HID
constexpr size_t OH_W1    = OH_XMOD  + (size_t)L * HID;          // W1N*HID
constexpr size_t OH_W2    = OH_W1    + (size_t)W1N * HID;        // HID*FW
constexpr size_t OH_IPKW  = OH_W2    + (size_t)HID * FW;         // HID*CTX
constexpr size_t OH_IPVW  = OH_IPKW  + (size_t)HID * CTX;
constexpr size_t OH_IP    = OH_IPVW  + (size_t)HID * CTX;        // LIP*CTX
constexpr size_t OH_QR    = OH_IP    + (size_t)LIP * CTX;        // HQ
constexpr size_t OH_KR    = OH_QR    + HQ;
constexpr size_t OH_QNR   = OH_KR    + HQ;
constexpr size_t OH_VT    = OH_QNR   + HQ;
constexpr size_t OH_IPK   = OH_VT    + HQ;                       // H*LIP*D
constexpr size_t OH_IPVT  = OH_IPK   + (size_t)H * LIP * D;
constexpr size_t OH_FUSED = OH_IPVT  + (size_t)H * LIP * D;      // L*FW
constexpr size_t OH_QKV   = OH_FUSED + (size_t)L * FW;           // L*QKV
constexpr size_t SCRATCH_H = OH_QKV + (size_t)L * QKV;

__device__ __align__(16) __half g_hscratch[SCRATCH_H];

// ---------------------------------------------------------------------------
// Helpers
// ---------------------------------------------------------------------------
__device__ __forceinline__ void mma16(float* c, const uint32_t* a,
                                      uint32_t b0, uint32_t b1) {
    asm volatile(
        "mma.sync.aligned.m16n8k16.row.col.f32.f16.f16.f32 "
        "{%0,%1,%2,%3}, {%4,%5,%6,%7}, {%8,%9}, {%0,%1,%2,%3};\n"
        : "+f"(c[0]), "+f"(c[1]), "+f"(c[2]), "+f"(c[3])
        : "r"(a[0]), "r"(a[1]), "r"(a[2]), "r"(a[3]),
          "r"(b0), "r"(b1));
}

__device__ __forceinline__ void ldsm_x4(uint32_t* r, uint32_t addr) {
    asm volatile("ldmatrix.sync.aligned.m8n8.x4.shared.b16 {%0,%1,%2,%3}, [%4];"
                 : "=r"(r[0]), "=r"(r[1]), "=r"(r[2]), "=r"(r[3])
                 : "r"(addr));
}

__device__ __forceinline__ void cp_async16(uint32_t dst, const void* src, bool pred) {
    int bytes = pred ? 16 : 0;
    asm volatile("cp.async.cg.shared.global [%0], [%1], 16, %2;\n"
                 :: "r"(dst), "l"(src), "r"(bytes));
}

__device__ __forceinline__ uint32_t pack_h2(float x, float y) {
    __half2 h = __floats2half2_rn(x, y);
    return *(uint32_t*)&h;
}

__device__ __forceinline__ float blockReduceSum(float v, float* sh) {
    #pragma unroll
    for (int o = 16; o; o >>= 1) v += __shfl_xor_sync(0xffffffffu, v, o);
    int lane = threadIdx.x & 31, w = threadIdx.x >> 5;
    __syncthreads();
    if (lane == 0) sh[w] = v;
    __syncthreads();
    float r = 0.f;
    int nw = blockDim.x >> 5;
    for (int i = 0; i < nw; i++) r += sh[i];
    return r;
}

__device__ __forceinline__ float gelu_tanh(float x) {
    float t  = 0.7978845608028654f * (x + 0.044715f * x * x * x);
    float th = 1.f - 2.f / (__expf(2.f * t) + 1.f);
    return 0.5f * x * (1.0f + th);
}

__device__ __forceinline__ float4 h4_to_f4(const __half* p) {
    uint2 u = *(const uint2*)p;
    __half2 a = *(__half2*)&u.x, b = *(__half2*)&u.y;
    return make_float4(__low2float(a), __high2float(a),
                       __low2float(b), __high2float(b));
}

// ---------------------------------------------------------------------------
// fp16 GEMM (128x128 tile), 256 threads (2x4 warps, warp tile 64x32),
// cp.async 4-stage ring, ldmatrix, 80B rows, 2 CTAs/SM.
// Epilogue selected at COMPILE TIME (EPI):
//   0: C = acc (+bias)  (f32)
//   1: cols <  fuseStart: half(acc+bias) -> ((half*)C)[row*QKV + col]
//      cols >= fuseStart: gelu(acc+bias) -> half -> gOut[row][HID+col-fuseStart]
// ---------------------------------------------------------------------------
constexpr int GSTAGES   = 4;
constexpr int ROWB      = 80;
constexpr int TILE_B    = 128 * ROWB;           // 10240
constexpr int STAGE_B   = 2 * TILE_B;           // 20480
constexpr uint32_t GEMM_SMEM = GSTAGES * STAGE_B;   // 80KB

template <int EPI>
__global__ void __launch_bounds__(256, 2) gemm_f16_kernel(
    const __half* __restrict__ A, const __half* __restrict__ B,
    float* __restrict__ C, const float* __restrict__ bias,
    int M, int N, int K, int lda, int ldb, int ldc,
    size_t sA, size_t sB, size_t sC,
    int nTiles, int mc,
    __half* __restrict__ gOut, int fuseStart)
{
    extern __shared__ __align__(128) uint8_t dsm[];
    uint32_t smBase = (uint32_t)__cvta_generic_to_shared(dsm);

    A += (size_t)blockIdx.z * sA;
    B += (size_t)blockIdx.z * sB;
    C += (size_t)blockIdx.z * sC;

    int bx    = blockIdx.x;
    int per   = mc * nTiles;
    int chunk = bx / per;
    int rem   = bx - chunk * per;
    int nTile = rem / mc;
    int mTile = chunk * mc + (rem - nTile * mc);
    int aBase = mTile * 128;
    int bBase = nTile * 128;

    int tid  = threadIdx.x;
    int lane = tid & 31, warp = tid >> 5;
    int wm   = warp >> 2, wn = warp & 3;

    int kt = K >> 5;

    int r0  = tid >> 2;
    int r1  = r0 + 64;
    int c16 = tid & 3;
    bool pa0 = aBase + r0 < M, pa1 = aBase + r1 < M;
    bool pb0 = bBase + r0 < N, pb1 = bBase + r1 < N;
    const __half* Ap0 = A + (size_t)(pa0 ? aBase + r0 : 0) * lda + c16 * 8;
    const __half* Ap1 = A + (size_t)(pa1 ? aBase + r1 : 0) * lda + c16 * 8;
    const __half* Bp0 = B + (size_t)(pb0 ? bBase + r0 : 0) * ldb + c16 * 8;
    const __half* Bp1 = B + (size_t)(pb1 ? bBase + r1 : 0) * ldb + c16 * 8;

    uint32_t off0 = (uint32_t)(r0 * ROWB + c16 * 16);
    uint32_t off1 = (uint32_t)(r1 * ROWB + c16 * 16);

    uint32_t aOff = (uint32_t)((wm * 64 + (lane & 15)) * ROWB + (lane >> 4) * 16);
    uint32_t bOff = (uint32_t)(TILE_B + (wn * 32 + (lane & 15)) * ROWB + (lane >> 4) * 16);

#define GEMM_PREF(itv) do {                                                   \
    int _it = (itv);                                                          \
    if (_it < kt) {                                                           \
        int _ko = _it << 5;                                                   \
        uint32_t _sA = smBase + (uint32_t)(_it % GSTAGES) * STAGE_B;          \
        uint32_t _sB = _sA + (uint32_t)TILE_B;                                \
        cp_async16(_sA + off0, Ap0 + _ko, pa0);                               \
        cp_async16(_sA + off1, Ap1 + _ko, pa1);                               \
        cp_async16(_sB + off0, Bp0 + _ko, pb0);                               \
        cp_async16(_sB + off1, Bp1 + _ko, pb1);                               \
    }                                                                         \
    asm volatile("cp.async.commit_group;\n" ::);                              \
} while (0)

    float acc[4][4][4];
    #pragma unroll
    for (int i = 0; i < 4; i++)
        #pragma unroll
        for (int j = 0; j < 4; j++)
            #pragma unroll
            for (int t = 0; t < 4; t++) acc[i][j][t] = 0.f;

    GEMM_PREF(0);
    GEMM_PREF(1);
    GEMM_PREF(2);

    for (int it = 0; it < kt; ++it) {
        asm volatile("cp.async.wait_group 2;\n" ::);
        __syncthreads();
        GEMM_PREF(it + 3);

        uint32_t stage = smBase + (uint32_t)(it % GSTAGES) * STAGE_B;
        uint32_t aA = stage + aOff;
        uint32_t bA = stage + bOff;

        #pragma unroll
        for (int kk = 0; kk < 2; kk++) {
            uint32_t a[4][4], b[2][4];
            #pragma unroll
            for (int mt = 0; mt < 4; mt++)
                ldsm_x4(a[mt], aA + mt * (16 * ROWB) + kk * 32);
            #pragma unroll
            for (int np = 0; np < 2; np++)
                ldsm_x4(b[np], bA + np * (16 * ROWB) + kk * 32);
            #pragma unroll
            for (int mt = 0; mt < 4; mt++)
                #pragma unroll
                for (int nt = 0; nt < 4; nt++)
                    mma16(acc[mt][nt], a[mt],
                          b[nt >> 1][nt & 1], b[nt >> 1][(nt & 1) + 2]);
        }
    }
#undef GEMM_PREF

    int gid = lane >> 2, tig = lane & 3;
    #pragma unroll
    for (int mt = 0; mt < 4; mt++) {
        #pragma unroll
        for (int nt = 0; nt < 4; nt++) {
            int row = aBase + wm * 64 + mt * 16 + gid;
            int col = bBase + wn * 32 + nt * 8 + tig * 2;
            if (col < N) {
                float b0 = 0.f, b1 = 0.f;
                if (bias) { b0 = bias[col]; b1 = bias[col + 1]; }
                float v0 = acc[mt][nt][0] + b0, v1 = acc[mt][nt][1] + b1;
                float v2 = acc[mt][nt][2] + b0, v3 = acc[mt][nt][3] + b1;
                if constexpr (EPI == 1) {
                    if (col >= fuseStart) {
                        int fcol = HID + col - fuseStart;
                        if (row < M)
                            *(__half2*)(gOut + (size_t)row * FW + fcol) =
                                __floats2half2_rn(gelu_tanh(v0), gelu_tanh(v1));
                        if (row + 8 < M)
                            *(__half2*)(gOut + (size_t)(row + 8) * FW + fcol) =
                                __floats2half2_rn(gelu_tanh(v2), gelu_tanh(v3));
                    } else {
                        __half* qk = (__half*)C;
                        if (row < M)
                            *(__half2*)(qk + (size_t)row * QKV + col) =
                                __floats2half2_rn(v0, v1);
                        if (row + 8 < M)
                            *(__half2*)(qk + (size_t)(row + 8) * QKV + col) =
                                __floats2half2_rn(v2, v3);
                    }
                } else {
                    if (row < M) {
                        C[(size_t)row * ldc + col]     = v0;
                        C[(size_t)row * ldc + col + 1] = v1;
                    }
                    if (row + 8 < M) {
                        C[(size_t)(row + 8) * ldc + col]     = v2;
                        C[(size_t)(row + 8) * ldc + col + 1] = v3;
                    }
                }
            }
        }
    }
}

// ---------------------------------------------------------------------------
// Flash attention (self-attn): per CTA = (head, 128-row Q block) -> attn1 f32
// ---------------------------------------------------------------------------
constexpr int FROWB = 272;
constexpr uint32_t FTILE = 128 * FROWB;             // 34816
constexpr uint32_t FLASH_SMEM = 3 * FTILE;          // 104448

__global__ void __launch_bounds__(256) flash_kernel(
    const __half* __restrict__ Qg, const __half* __restrict__ Kg,
    const __half* __restrict__ Vg, float* __restrict__ Og)
{
    extern __shared__ __align__(128) uint8_t fsm[];
    uint32_t sQ = (uint32_t)__cvta_generic_to_shared(fsm);
    uint32_t sK = sQ + FTILE;
    uint32_t sV = sK + FTILE;

    int head = blockIdx.y;
    int qb   = blockIdx.x * 128;
    const __half* Qp = Qg + ((size_t)head * L + qb) * D;
    const __half* Kp = Kg + (size_t)head * L * D;
    const __half* Vp = Vg + (size_t)head * D * L;

    int tid = threadIdx.x, lane = tid & 31, warp = tid >> 5;
    int lr = tid >> 1;
    int lc = (tid & 1) * 8;
    uint32_t ldst = (uint32_t)(lr * FROWB + lc * 16);

#define FLOAD(dst, gbase, gstride) do {                                       \
    const __half* _g = (gbase) + (size_t)lr * (gstride) + lc * 8;             \
    _Pragma("unroll")                                                         \
    for (int _j = 0; _j < 8; _j++)                                            \
        cp_async16((dst) + ldst + _j * 16, _g + _j * 8, true);                \
} while (0)

    FLOAD(sQ, Qp, D);
    FLOAD(sK, Kp, D);
    asm volatile("cp.async.commit_group;\n" ::);
    FLOAD(sV, Vp, L);
    asm volatile("cp.async.commit_group;\n" ::);
    asm volatile("cp.async.wait_group 1;\n" ::);
    __syncthreads();

    uint32_t qf[8][4];
    {
        uint32_t qa = sQ + (uint32_t)((warp * 16 + (lane & 15)) * FROWB
                                      + (lane >> 4) * 16);
        #pragma unroll
        for (int kk = 0; kk < 8; kk++) ldsm_x4(qf[kk], qa + kk * 32);
    }

    float o[16][4];
    #pragma unroll
    for (int i = 0; i < 16; i++) { o[i][0] = o[i][1] = o[i][2] = o[i][3] = 0.f; }
    float mr0 = -1e30f, mr1 = -1e30f, l0 = 0.f, l1 = 0.f;

    uint32_t kba = sK + (uint32_t)((lane & 15) * FROWB + (lane >> 4) * 16);
    uint32_t vba = sV + (uint32_t)((lane & 15) * FROWB + (lane >> 4) * 16);

    constexpr int NKB = L / 128;    // 16
    for (int kb = 0; kb < NKB; kb++) {
        float s[16][4];
        #pragma unroll
        for (int i = 0; i < 16; i++) { s[i][0] = s[i][1] = s[i][2] = s[i][3] = 0.f; }
        #pragma unroll
        for (int kk = 0; kk < 8; kk++) {
            #pragma unroll
            for (int np = 0; np < 8; np++) {
                uint32_t b[4];
                ldsm_x4(b, kba + np * (16 * FROWB) + kk * 32);
                mma16(s[2 * np],     qf[kk], b[0], b[2]);
                mma16(s[2 * np + 1], qf[kk], b[1], b[3]);
            }
        }
        __syncthreads();
        if (kb + 1 < NKB) FLOAD(sK, Kp + (size_t)(kb + 1) * 128 * D, D);
        asm volatile("cp.async.commit_group;\n" ::);

        float m0 = -1e30f, m1 = -1e30f;
        #pragma unroll
        for (int ng = 0; ng < 16; ng++) {
            m0 = fmaxf(m0, fmaxf(s[ng][0], s[ng][1]));
            m1 = fmaxf(m1, fmaxf(s[ng][2], s[ng][3]));
        }
        m0 = fmaxf(m0, __shfl_xor_sync(0xffffffffu, m0, 1));
        m0 = fmaxf(m0, __shfl_xor_sync(0xffffffffu, m0, 2));
        m1 = fmaxf(m1, __shfl_xor_sync(0xffffffffu, m1, 1));
        m1 = fmaxf(m1, __shfl_xor_sync(0xffffffffu, m1, 2));
        float nm0 = fmaxf(mr0, m0), nm1 = fmaxf(mr1, m1);
        float a0 = __expf(mr0 - nm0), a1 = __expf(mr1 - nm1);
        mr0 = nm0; mr1 = nm1;
        float ps0 = 0.f, ps1 = 0.f;
        #pragma unroll
        for (int ng = 0; ng < 16; ng++) {
            s[ng][0] = __expf(s[ng][0] - nm0);
            s[ng][1] = __expf(s[ng][1] - nm0);
            s[ng][2] = __expf(s[ng][2] - nm1);
            s[ng][3] = __expf(s[ng][3] - nm1);
            ps0 += s[ng][0] + s[ng][1];
            ps1 += s[ng][2] + s[ng][3];
            o[ng][0] *= a0; o[ng][1] *= a0;
            o[ng][2] *= a1; o[ng][3] *= a1;
        }
        l0 = l0 * a0 + ps0;
        l1 = l1 * a1 + ps1;

        uint32_t pa[8][4];
        #pragma unroll
        for (int kk = 0; kk < 8; kk++) {
            pa[kk][0] = pack_h2(s[2 * kk][0],     s[2 * kk][1]);
            pa[kk][1] = pack_h2(s[2 * kk][2],     s[2 * kk][3]);
            pa[kk][2] = pack_h2(s[2 * kk + 1][0], s[2 * kk + 1][1]);
            pa[kk][3] = pack_h2(s[2 * kk + 1][2], s[2 * kk + 1][3]);
        }

        asm volatile("cp.async.wait_group 1;\n" ::);
        __syncthreads();

        #pragma unroll
        for (int kk = 0; kk < 8; kk++) {
            #pragma unroll
            for (int np = 0; np < 8; np++) {
                uint32_t b[4];
                ldsm_x4(b, vba + np * (16 * FROWB) + kk * 32);
                mma16(o[2 * np],     pa[kk], b[0], b[2]);
                mma16(o[2 * np + 1], pa[kk], b[1], b[3]);
            }
        }
        __syncthreads();
        if (kb + 1 < NKB) FLOAD(sV, Vp + (kb + 1) * 128, L);
        asm volatile("cp.async.commit_group;\n" ::);
        asm volatile("cp.async.wait_group 1;\n" ::);
        __syncthreads();
    }
#undef FLOAD

    l0 += __shfl_xor_sync(0xffffffffu, l0, 1);
    l0 += __shfl_xor_sync(0xffffffffu, l0, 2);
    l1 += __shfl_xor_sync(0xffffffffu, l1, 1);
    l1 += __shfl_xor_sync(0xffffffffu, l1, 2);
    float inv0 = 1.f / l0, inv1 = 1.f / l1;
    int gid = lane >> 2, tig = lane & 3;
    int r0 = qb + warp * 16 + gid;
    float* O0 = Og + ((size_t)head * L + r0) * D;
    float* O1 = O0 + 8 * D;
    #pragma unroll
    for (int ng = 0; ng < 16; ng++) {
        int col = ng * 8 + tig * 2;
        O0[col]     = o[ng][0] * inv0;
        O0[col + 1] = o[ng][1] * inv0;
        O1[col]     = o[ng][2] * inv1;
        O1[col + 1] = o[ng][3] * inv1;
    }
}

// ---------------------------------------------------------------------------
// IP flash attention + attn combine into fused buffer (half). 2 CTAs/SM.
// ---------------------------------------------------------------------------
constexpr int IPVROWB = 144;
constexpr uint32_t IPK_B = 64 * FROWB;              // 17408
constexpr uint32_t IPV_B = 128 * IPVROWB;           // 18432
constexpr uint32_t IPF_SMEM = FTILE + IPK_B + IPV_B;   // 70656

__global__ void __launch_bounds__(256, 2) ip_flash_kernel(
    const __half* __restrict__ Qg, const __half* __restrict__ Kg,
    const __half* __restrict__ Vg, const float* __restrict__ attn1,
    const float* __restrict__ ip_scale, __half* __restrict__ fused)
{
    extern __shared__ __align__(128) uint8_t fsm[];
    uint32_t sQ = (uint32_t)__cvta_generic_to_shared(fsm);
    uint32_t sK = sQ + FTILE;
    uint32_t sV = sK + IPK_B;

    int head = blockIdx.y;
    int qb   = blockIdx.x * 128;
    const __half* Qp = Qg + ((size_t)head * L + qb) * D;
    const __half* Kp = Kg + (size_t)head * LIP * D;
    const __half* Vp = Vg + (size_t)head * D * LIP;

    int tid = threadIdx.x, lane = tid & 31, warp = tid >> 5;

    {
        int lr = tid >> 1, lc = (tid & 1) * 8;
        const __half* g = Qp + (size_t)lr * D + lc * 8;
        uint32_t dst = sQ + (uint32_t)(lr * FROWB + lc * 16);
        #pragma unroll
        for (int j = 0; j < 8; j++) cp_async16(dst + j * 16, g + j * 8, true);
    }
    {
        int kr = tid >> 2, kc = (tid & 3) * 4;
        const __half* g = Kp + (size_t)kr * D + kc * 8;
        uint32_t dst = sK + (uint32_t)(kr * FROWB + kc * 16);
        #pragma unroll
        for (int j = 0; j < 4; j++) cp_async16(dst + j * 16, g + j * 8, true);
    }
    {
        int vr = tid >> 1, vc = (tid & 1) * 4;
        const __half* g = Vp + (size_t)vr * LIP + vc * 8;
        uint32_t dst = sV + (uint32_t)(vr * IPVROWB + vc * 16);
        #pragma unroll
        for (int j = 0; j < 4; j++) cp_async16(dst + j * 16, g + j * 8, true);
    }
    asm volatile("cp.async.commit_group;\n" ::);
    asm volatile("cp.async.wait_group 0;\n" ::);
    __syncthreads();

    uint32_t qf[8][4];
    {
        uint32_t qa = sQ + (uint32_t)((warp * 16 + (lane & 15)) * FROWB
                                      + (lane >> 4) * 16);
        #pragma unroll
        for (int kk = 0; kk < 8; kk++) ldsm_x4(qf[kk], qa + kk * 32);
    }

    float s[8][4];
    #pragma unroll
    for (int i = 0; i < 8; i++) { s[i][0] = s[i][1] = s[i][2] = s[i][3] = 0.f; }
    uint32_t kba = sK + (uint32_t)((lane & 15) * FROWB + (lane >> 4) * 16);
    #pragma unroll
    for (int kk = 0; kk < 8; kk++) {
        #pragma unroll
        for (int np = 0; np < 4; np++) {
            uint32_t b[4];
            ldsm_x4(b, kba + np * (16 * FROWB) + kk * 32);
            mma16(s[2 * np],     qf[kk], b[0], b[2]);
            mma16(s[2 * np + 1], qf[kk], b[1], b[3]);
        }
    }

    float m0 = -1e30f, m1 = -1e30f;
    #pragma unroll
    for (int ng = 0; ng < 8; ng++) {
        m0 = fmaxf(m0, fmaxf(s[ng][0], s[ng][1]));
        m1 = fmaxf(m1, fmaxf(s[ng][2], s[ng][3]));
    }
    m0 = fmaxf(m0, __shfl_xor_sync(0xffffffffu, m0, 1));
    m0 = fmaxf(m0, __shfl_xor_sync(0xffffffffu, m0, 2));
    m1 = fmaxf(m1, __shfl_xor_sync(0xffffffffu, m1, 1));
    m1 = fmaxf(m1, __shfl_xor_sync(0xffffffffu, m1, 2));
    float l0 = 0.f, l1 = 0.f;
    #pragma unroll
    for (int ng = 0; ng < 8; ng++) {
        s[ng][0] = __expf(s[ng][0] - m0);
        s[ng][1] = __expf(s[ng][1] - m0);
        s[ng][2] = __expf(s[ng][2] - m1);
        s[ng][3] = __expf(s[ng][3] - m1);
        l0 += s[ng][0] + s[ng][1];
        l1 += s[ng][2] + s[ng][3];
    }
    uint32_t pa[4][4];
    #pragma unroll
    for (int kk = 0; kk < 4; kk++) {
        pa[kk][0] = pack_h2(s[2 * kk][0],     s[2 * kk][1]);
        pa[kk][1] = pack_h2(s[2 * kk][2],     s[2 * kk][3]);
        pa[kk][2] = pack_h2(s[2 * kk + 1][0], s[2 * kk + 1][1]);
        pa[kk][3] = pack_h2(s[2 * kk + 1][2], s[2 * kk + 1][3]);
    }

    float o[16][4];
    #pragma unroll
    for (int i = 0; i < 16; i++) { o[i][0] = o[i][1] = o[i][2] = o[i][3] = 0.f; }
    uint32_t vba = sV + (uint32_t)((lane & 15) * IPVROWB + (lane >> 4) * 16);
    #pragma unroll
    for (int kk = 0; kk < 4; kk++) {
        #pragma unroll
        for (int np = 0; np < 8; np++) {
            uint32_t b[4];
            ldsm_x4(b, vba + np * (16 * IPVROWB) + kk * 32);
            mma16(o[2 * np],     pa[kk], b[0], b[2]);
            mma16(o[2 * np + 1], pa[kk], b[1], b[3]);
        }
    }

    l0 += __shfl_xor_sync(0xffffffffu, l0, 1);
    l0 += __shfl_xor_sync(0xffffffffu, l0, 2);
    l1 += __shfl_xor_sync(0xffffffffu, l1, 1);
    l1 += __shfl_xor_sync(0xffffffffu, l1, 2);
    float sc = ip_scale[0];
    float inv0 = sc / l0, inv1 = sc / l1;
    int gid = lane >> 2, tig = lane & 3;
    int r0 = qb + warp * 16 + gid;
    const float* A0 = attn1 + ((size_t)head * L + r0) * D;
    const float* A1 = A0 + 8 * D;
    __half* F0 = fused + (size_t)r0 * FW + head * D;
    __half* F1 = F0 + (size_t)8 * FW;
    #pragma unroll
    for (int ng = 0; ng < 16; ng++) {
        int col = ng * 8 + tig * 2;
        *(__half2*)(F0 + col) = __floats2half2_rn(
            A0[col] + o[ng][0] * inv0, A0[col + 1] + o[ng][1] * inv0);
        *(__half2*)(F1 + col) = __floats2half2_rn(
            A1[col] + o[ng][2] * inv1, A1[col + 1] + o[ng][3] * inv1);
    }
}

// ---------------------------------------------------------------------------
// float -> half conversion, 8 elems per thread
// ---------------------------------------------------------------------------
__global__ __launch_bounds__(256) void f2h_kernel(
    const float* __restrict__ in, __half* __restrict__ out, int n)
{
    int i = (blockIdx.x * 256 + threadIdx.x) * 8;
    if (i < n) {
        float4 a = *(const float4*)(in + i);
        float4 b = *(const float4*)(in + i + 4);
        __half2 h[4];
        h[0] = __floats2half2_rn(a.x, a.y);
        h[1] = __floats2half2_rn(a.z, a.w);
        h[2] = __floats2half2_rn(b.x, b.y);
        h[3] = __floats2half2_rn(b.z, b.w);
        *(uint4*)(out + i) = *(uint4*)h;
    }
}

// ---------------------------------------------------------------------------
// mod = silu(vec) @ mod_lin_w^T + mod_lin_b
// ---------------------------------------------------------------------------
__global__ __launch_bounds__(256) void mod_gemv_kernel(
    const float* __restrict__ vec, const float* __restrict__ W,
    const float* __restrict__ b, float* __restrict__ mod)
{
    __shared__ float sv[HID];
    int tid = threadIdx.x;
    for (int i = tid; i < HID; i += 256) {
        float x = vec[i];
        sv[i] = x / (1.f + __expf(-x));
    }
    __syncthreads();
    int warp = tid >> 5, lane = tid & 31;
    int n = blockIdx.x * 8 + warp;
    const float* wrow = W + (size_t)n * HID;
    float s = 0.f;
    for (int k = lane * 4; k < HID; k += 128) {
        float4 w4 = *(const float4*)(wrow + k);
        s += sv[k] * w4.x + sv[k + 1] * w4.y + sv[k + 2] * w4.z + sv[k + 3] * w4.w;
    }
    #pragma unroll
    for (int o = 16; o; o >>= 1) s += __shfl_xor_sync(0xffffffffu, s, o);
    if (lane == 0) mod[n] = s + b[n];
}

// ---------------------------------------------------------------------------
// x_mod = (1+scale)*layernorm(x) + shift  -> half
// ---------------------------------------------------------------------------
__global__ __launch_bounds__(256) void ln_mod_kernel(
    const float* __restrict__ x, const float* __restrict__ mod,
    __half* __restrict__ xmod)
{
    __shared__ float sh[8];
    int l = blockIdx.x, tid = threadIdx.x;
    const float* row = x + (size_t)l * HID;
    float v[12];
    float s = 0.f, sq = 0.f;
    #pragma unroll
    for (int i = 0; i < 12; i++) {
        v[i] = row[tid + i * 256];
        s += v[i];
        sq += v[i] * v[i];
    }
    s  = blockReduceSum(s, sh);
    sq = blockReduceSum(sq, sh);
    float mu   = s * (1.f / HID);
    float var  = sq * (1.f / HID) - mu * mu;
    float rstd = rsqrtf(var + 1e-6f);
    #pragma unroll
    for (int i = 0; i < 12; i++) {
        int c = tid + i * 256;
        float xn = (v[i] - mu) * rstd;
        xmod[(size_t)l * HID + c] = __float2half((1.f + mod[HID + c]) * xn + mod[c]);
    }
}

// ---------------------------------------------------------------------------
// rmsnorm(q,k) + rope + repack, reading half QKV. One warp per (head, l);
// block = 8 consecutive l of ONE head. vt staged via smem, coalesced writes.
// ---------------------------------------------------------------------------
__global__ __launch_bounds__(256) void rms_rope_kernel(
    const __half* __restrict__ qkv, const float* __restrict__ pe,
    const float* __restrict__ qsc, const float* __restrict__ ksc,
    __half* __restrict__ qr, __half* __restrict__ kr,
    __half* __restrict__ qnr, __half* __restrict__ vt)
{
    __shared__ float sv[8][132];
    int tid = threadIdx.x, lane = tid & 31, warp = tid >> 5;
    int g = blockIdx.x * 8 + warp;          // g = head * L + l
    int head = g >> 11;                     // L = 2048
    int l    = g & (L - 1);

    const __half* base = qkv + (size_t)l * QKV + head * D + lane * 4;
    float4 q = h4_to_f4(base);
    float4 k = h4_to_f4(base + HID);
    float4 v = h4_to_f4(base + 2 * HID);

    float sq = q.x * q.x + q.y * q.y + q.z * q.z + q.w * q.w;
    float sk = k.x * k.x + k.y * k.y + k.z * k.z + k.w * k.w;
    #pragma unroll
    for (int o = 16; o; o >>= 1) {
        sq += __shfl_xor_sync(0xffffffffu, sq, o);
        sk += __shfl_xor_sync(0xffffffffu, sk, o);
    }
    float rq = rsqrtf(sq * (1.f / D) + 1e-6f) * 0.08838834764831845f;
    float rk = rsqrtf(sk * (1.f / D) + 1e-6f);

    float4 qs4 = *(const float4*)(qsc + lane * 4);
    float4 ks4 = *(const float4*)(ksc + lane * 4);
    float4 qn = make_float4(q.x * rq * qs4.x, q.y * rq * qs4.y,
                            q.z * rq * qs4.z, q.w * rq * qs4.w);
    float4 kn = make_float4(k.x * rk * ks4.x, k.y * rk * ks4.y,
                            k.z * rk * ks4.z, k.w * rk * ks4.w);

    size_t oidx = ((size_t)head * L + l) * D + lane * 4;
    *(__half2*)(qnr + oidx)     = __floats2half2_rn(qn.x, qn.y);
    *(__half2*)(qnr + oidx + 2) = __floats2half2_rn(qn.z, qn.w);

    const float* pb = pe + ((size_t)l * (D / 2) + lane * 2) * 4;
    float4 p0 = *(const float4*)(pb);
    float4 p1 = *(const float4*)(pb + 4);

    float4 qo, ko;
    qo.x = p0.x * qn.x + p0.y * qn.y;  qo.y = p0.z * qn.x + p0.w * qn.y;
    qo.z = p1.x * qn.z + p1.y * qn.w;  qo.w = p1.z * qn.z + p1.w * qn.w;
    ko.x = p0.x * kn.x + p0.y * kn.y;  ko.y = p0.z * kn.x + p0.w * kn.y;
    ko.z = p1.x * kn.z + p1.y * kn.w;  ko.w = p1.z * kn.z + p1.w * kn.w;

    *(__half2*)(qr + oidx)     = __floats2half2_rn(qo.x, qo.y);
    *(__half2*)(qr + oidx + 2) = __floats2half2_rn(qo.z, qo.w);
    *(__half2*)(kr + oidx)     = __floats2half2_rn(ko.x, ko.y);
    *(__half2*)(kr + oidx + 2) = __floats2half2_rn(ko.z, ko.w);

    sv[warp][lane * 4]     = v.x;
    sv[warp][lane * 4 + 1] = v.y;
    sv[warp][lane * 4 + 2] = v.z;
    sv[warp][lane * 4 + 3] = v.w;
    __syncthreads();
    if (tid < D) {
        int d = tid;
        int l0 = (blockIdx.x * 8) & (L - 1);
        __half hv[8];
        #pragma unroll
        for (int j = 0; j < 8; j++) hv[j] = __float2half(sv[j][d]);
        *(uint4*)(vt + ((size_t)head * D + d) * L + l0) = *(uint4*)hv;
    }
}

// ---------------------------------------------------------------------------
// repack ip_k / ip_v GEMM outputs into per-head half layouts
// ---------------------------------------------------------------------------
__global__ __launch_bounds__(256) void repack_ip_kernel(
    const float* __restrict__ kraw, const float* __restrict__ vraw,
    __half* __restrict__ ipk, __half* __restrict__ ipvt)
{
    int i = blockIdx.x * 256 + threadIdx.x;
    int d = i & (D - 1);
    int lip = (i >> 7) & (LIP - 1);
    int head = i >> 13;
    size_t src = (size_t)lip * HID + head * D + d;
    ipk[((size_t)head * LIP + lip) * D + d]  = __float2half(kraw[src]);
    ipvt[((size_t)head * D + d) * LIP + lip] = __float2half(vraw[src]);
}

// ---------------------------------------------------------------------------
// split-K combine: out = x + gate[col] * (bias[col] + p0 + p1 + p2 + p3)
// NOTE: HID is NOT a power of two; col must use true modulo.
// ---------------------------------------------------------------------------
__global__ __launch_bounds__(256) void splitk_combine_kernel(
    const float* __restrict__ parts, const float* __restrict__ x,
    const float* __restrict__ mod_gate, const float* __restrict__ bias,
    float* __restrict__ out)
{
    int i4 = (blockIdx.x * 256 + threadIdx.x) * 4;     // < L*HID
    int col = i4 - (i4 / HID) * HID;
    const float4 p0 = *(const float4*)(parts + i4);
    const float4 p1 = *(const float4*)(parts + (size_t)L * HID + i4);
    const float4 p2 = *(const float4*)(parts + (size_t)2 * L * HID + i4);
    const float4 p3 = *(const float4*)(parts + (size_t)3 * L * HID + i4);
    const float4 xb = *(const float4*)(x + i4);
    const float4 gb = *(const float4*)(mod_gate + col);
    const float4 bb = *(const float4*)(bias + col);
    float4 r;
    r.x = xb.x + gb.x * (bb.x + p0.x + p1.x + p2.x + p3.x);
    r.y = xb.y + gb.y * (bb.y + p0.y + p1.y + p2.y + p3.y);
    r.z = xb.z + gb.z * (bb.z + p0.z + p1.z + p2.z + p3.z);
    r.w = xb.w + gb.w * (bb.w + p0.w + p1.w + p2.w + p3.w);
    *(float4*)(out + i4) = r;
}

// ---------------------------------------------------------------------------
// host side
// ---------------------------------------------------------------------------
template <int EPI>
static void launch_gemm_t(const __half* A, const __half* B, float* C, const float* bias,
                          int M, int N, int K, int lda, int ldb, int ldc,
                          size_t sA, size_t sB, size_t sC, int batch, int mc,
                          __half* gOut = nullptr, int fuseStart = 0)
{
    int mTiles = (M + 127) / 128, nTiles = (N + 127) / 128;
    if (mc > mTiles) mc = mTiles;
    dim3 grid(mTiles * nTiles, 1, batch);
    gemm_f16_kernel<EPI><<<grid, 256, GEMM_SMEM>>>(
        A, B, C, bias, M, N, K, lda, ldb, ldc,
        sA, sB, sC, nTiles, mc, gOut, fuseStart);
}

static void launch_f2h(const float* in, __half* out, size_t n)
{
    int blocks = (int)((n / 8 + 255) / 256);
    f2h_kernel<<<blocks, 256>>>(in, out, (int)n);
}

extern "C" void kernel_launch(void* const* d_in, const int* in_sizes, int n_in,
                              void* d_out, int out_size)
{
    const float* x          = (const float*)d_in[0];
    const float* vec        = (const float*)d_in[1];
    const float* pe         = (const float*)d_in[2];
    const float* image_proj = (const float*)d_in[3];
    const float* ip_scale   = (const float*)d_in[4];
    const float* mod_w      = (const float*)d_in[5];
    const float* mod_b      = (const float*)d_in[6];
    const float* w1         = (const float*)d_in[7];
    const float* b1         = (const float*)d_in[8];
    const float* w2         = (const float*)d_in[9];
    const float* b2         = (const float*)d_in[10];
    const float* qsc        = (const float*)d_in[11];
    const float* ksc        = (const float*)d_in[12];
    const float* ipkw       = (const float*)d_in[13];
    const float* ipvw       = (const float*)d_in[14];
    float* out = (float*)d_out;

    cudaFuncSetAttribute(gemm_f16_kernel<0>,
                         cudaFuncAttributeMaxDynamicSharedMemorySize, GEMM_SMEM);
    cudaFuncSetAttribute(gemm_f16_kernel<1>,
                         cudaFuncAttributeMaxDynamicSharedMemorySize, GEMM_SMEM);
    cudaFuncSetAttribute(flash_kernel,
                         cudaFuncAttributeMaxDynamicSharedMemorySize, FLASH_SMEM);
    cudaFuncSetAttribute(ip_flash_kernel,
                         cudaFuncAttributeMaxDynamicSharedMemorySize, IPF_SMEM);

    float* sc = nullptr;
    cudaGetSymbolAddress((void**)&sc, g_scratch);
    __half* hs = nullptr;
    cudaGetSymbolAddress((void**)&hs, g_hscratch);

    float* mod    = sc + O_MOD;
    float* attn1  = sc + O_ATTN1;
    float* ipkr   = sc + O_IPKR;
    float* ipvr   = sc + O_IPVR;
    float* parts  = sc + O_H;

    __half* h_xmod  = hs + OH_XMOD;
    __half* h_w1    = hs + OH_W1;
    __half* h_w2    = hs + OH_W2;
    __half* h_ipkw  = hs + OH_IPKW;
    __half* h_ipvw  = hs + OH_IPVW;
    __half* h_ip    = hs + OH_IP;
    __half* h_qr    = hs + OH_QR;
    __half* h_kr    = hs + OH_KR;
    __half* h_qnr   = hs + OH_QNR;
    __half* h_vt    = hs + OH_VT;
    __half* h_ipk   = hs + OH_IPK;
    __half* h_ipvt  = hs + OH_IPVT;
    __half* h_fused = hs + OH_FUSED;
    __half* h_qkv   = hs + OH_QKV;

    // [0] modulation vector
    mod_gemv_kernel<<<(3 * HID) / 8, 256>>>(vec, mod_w, mod_b, mod);
    // [1] w1 -> half
    launch_f2h(w1, h_w1, (size_t)W1N * HID);
    // [2] layernorm + modulate -> half
    ln_mod_kernel<<<L, 256>>>(x, mod, h_xmod);
    // [3] linear1: qkv -> half buffer, mlp -> gelu half into fused (ncu target)
    launch_gemm_t<1>(h_xmod, h_w1, (float*)h_qkv, b1, L, W1N, HID, HID, HID, W1N,
                     0, 0, 0, 1, 16, h_fused, QKV);
    // remaining conversions
    launch_f2h(w2, h_w2, (size_t)HID * FW);
    launch_f2h(ipkw, h_ipkw, (size_t)HID * CTX);
    launch_f2h(ipvw, h_ipvw, (size_t)HID * CTX);
    launch_f2h(image_proj, h_ip, (size_t)LIP * CTX);
    // rmsnorm + rope + repack (half in/out)
    rms_rope_kernel<<<(H * L) / 8, 256>>>(h_qkv, pe, qsc, ksc, h_qr, h_kr, h_qnr, h_vt);
    // ip_k / ip_v projections, batched (z=2)
    launch_gemm_t<0>(h_ip, h_ipkw, ipkr, nullptr, LIP, HID, CTX, CTX, CTX, HID,
                     0, (size_t)HID * CTX, (size_t)LIP * HID, 2, 1);
    repack_ip_kernel<<<(H * LIP * D) / 256, 256>>>(ipkr, ipvr, h_ipk, h_ipvt);
    // fused self-attention -> attn1 (f32)
    flash_kernel<<<dim3(L / 128, H), 256, FLASH_SMEM>>>(h_qr, h_kr, h_vt, attn1);
    // fused ip attention + combine -> fused attn section (half)
    ip_flash_kernel<<<dim3(L / 128, H), 256, IPF_SMEM>>>(
        h_qnr, h_ipk, h_ipvt, attn1, ip_scale, h_fused);
    // linear2 split-K=4
    launch_gemm_t<0>(h_fused, h_w2, parts, nullptr, L, HID, K2, FW, FW, HID,
                     (size_t)K2, (size_t)K2, (size_t)L * HID, KSPLIT, 8);
    // combine partials + bias + gate + residual -> out
    splitk_combine_kernel<<<(L * HID / 4) / 256, 256>>>(parts, x, mod + 2 * HID, b2, out);
}